// round 2
// baseline (speedup 1.0000x reference)
#include <cuda_runtime.h>
#include <math.h>

#define NCTA   128
#define NTHR   512
#define NWARP  16
#define TSTEPS 1000
#define BB     32
#define NN0    256
#define NN1    512
#define GG     4
#define NBARS  1000ULL
#define BARM   (NBARS * (unsigned long long)NCTA)

// Cross-step exchange buffers (ping-pong) + monotonic barrier counter.
__device__ float g_s0buf[2][NN0 * BB];
__device__ float g_spbuf[2][NN1 * BB];
__device__ unsigned long long g_arrive;

__global__ void __launch_bounds__(NTHR, 1)
rsnn_kernel(const float* __restrict__ inp,
            const float* __restrict__ W1,
            const float* __restrict__ Wr,
            float* __restrict__ out)
{
    __shared__ float wsh1[GG * NN0];          // 4 KB  (W1 rows of this CTA's 4 neurons)
    __shared__ float wshr[GG * NN1];          // 8 KB  (Wr rows)
    __shared__ float psum1[GG * NWARP * BB];  // 8 KB  (GEMM1 partials)
    __shared__ float psum2[GG * NWARP * BB];  // 8 KB  (GEMM2 partials)
    __shared__ unsigned long long sh_base;

    const int tid   = threadIdx.x;
    const int cta   = blockIdx.x;
    const int ws    = tid >> 5;
    const int lane  = tid & 31;
    const int mbase = cta * GG;

    // ---- one-time weight staging (persistent for all 1000 steps) ----
    for (int i = tid; i < GG * NN0; i += NTHR)
        wsh1[i] = W1[(mbase + (i >> 8)) * NN0 + (i & 255)];
    for (int i = tid; i < GG * NN1; i += NTHR)
        wshr[i] = Wr[(mbase + (i >> 9)) * NN1 + (i & 511)];

    // ---- launch-consistent barrier base: g_arrive is a multiple of BARM at
    // launch start; at most NCTA-1 stray arrivals (< BARM) can be seen before
    // every CTA has read its base (barrier 0 gates all further arrivals). ----
    if (tid == 0) {
        unsigned long long g = *(volatile unsigned long long*)&g_arrive;
        sh_base = (g / BARM) * BARM;
    }

    // ---- zero the parity-1 buffers (read at t=0 as the initial delay state) ----
    {
        const int per   = (NN0 * BB + NN1 * BB) / NCTA;  // 192
        const int start = cta * per;
        for (int i = tid; i < per; i += NTHR) {
            int idx = start + i;
            if (idx < NN0 * BB) g_s0buf[1][idx] = 0.0f;
            else                g_spbuf[1][idx - NN0 * BB] = 0.0f;
        }
    }
    __syncthreads();
    const unsigned long long base = sh_base;

#define GRID_BARRIER(bid) do {                                                   \
        __syncthreads();                                                         \
        if (tid == 0) {                                                          \
            __threadfence();                                                     \
            atomicAdd(&g_arrive, 1ULL);                                          \
            unsigned long long tgt =                                             \
                base + (unsigned long long)((bid) + 1) * NCTA;                   \
            while (*(volatile unsigned long long*)&g_arrive < tgt) {             \
                __nanosleep(20);                                                 \
            }                                                                    \
            __threadfence();                                                     \
        }                                                                        \
        __syncthreads();                                                         \
    } while (0)

    // ---- GLIF constants (match reference's python-double folding -> fp32) ----
    const float CID = 0.95f;                                      // 1 - DT*KSYN
    const float CIA = 0.05f;                                      // DT*KSYN
    const float CVD = 0.99f;                                      // 1 - DT*KM
    const float CVA = (float)(0.05 * (1.0 / 5.0) * (1.0 / 9.43)); // DT*KM*R
    const float TH  = (float)(10.0 * 1.0986122886681098);         // 10*ln(3)
    const float AD0 = (float)(1.0 - 0.05 * 0.003);
    const float AD1 = (float)(1.0 - 0.05 * 0.1);
    const float AA0 = (float)(-9.18 * 0.05);
    const float AA1 = (float)(-198.94 * 0.05);

    // ---- recurrent state in registers ----
    float V1 = 0.f, I1 = 0.f, A10 = 0.f, A11 = 0.f;   // layer-1 (tid < 128)
    float V0 = 0.f, I0 = 0.f, A00 = 0.f, A01 = 0.f;   // layer-0 (tid 128..191)

    // layer-0 element owned by threads 128..191 (fixed for whole run)
    const int l0id = cta * 64 + (tid - GG * BB);
    const int l0b  = l0id >> 8;
    const int l0n  = l0id & 255;

    GRID_BARRIER(0);

    for (int t = 0; t < TSTEPS; ++t) {
        const float* __restrict__ s0r = g_s0buf[(t & 1) ^ 1];
        const float* __restrict__ spr = g_spbuf[(t & 1) ^ 1];

        // ---- hoist layer-0 input load: overlap DRAM latency with GEMM ----
        float x0 = 0.0f;
        if (tid >= GG * BB && tid < GG * BB + 64)
            x0 = __ldg(&inp[t * (BB * NN0) + l0b * NN0 + l0n]);

        // ---- preload this warp's activation slices (L2-coherent loads, MLP) ----
        const int n1b = ws * (NN0 / NWARP);  // 16-wide slice of N0
        const int n2b = ws * (NN1 / NWARP);  // 32-wide slice of N1
        float xv1[16], xv2[32];
#pragma unroll
        for (int k = 0; k < 16; ++k) xv1[k] = __ldcg(&s0r[(n1b + k) * BB + lane]);
#pragma unroll
        for (int k = 0; k < 32; ++k) xv2[k] = __ldcg(&spr[(n2b + k) * BB + lane]);

        // ---- GEMM partials: lane = batch, G=4 neurons reuse each x value ----
        float acc1[GG] = {0.f, 0.f, 0.f, 0.f};
        float acc2[GG] = {0.f, 0.f, 0.f, 0.f};
#pragma unroll
        for (int q = 0; q < 4; ++q) {
#pragma unroll
            for (int g = 0; g < GG; ++g) {
                float4 w = *(const float4*)&wsh1[g * NN0 + n1b + q * 4];
                acc1[g] = fmaf(w.x, xv1[q * 4 + 0], acc1[g]);
                acc1[g] = fmaf(w.y, xv1[q * 4 + 1], acc1[g]);
                acc1[g] = fmaf(w.z, xv1[q * 4 + 2], acc1[g]);
                acc1[g] = fmaf(w.w, xv1[q * 4 + 3], acc1[g]);
            }
        }
#pragma unroll
        for (int q = 0; q < 8; ++q) {
#pragma unroll
            for (int g = 0; g < GG; ++g) {
                float4 w = *(const float4*)&wshr[g * NN1 + n2b + q * 4];
                acc2[g] = fmaf(w.x, xv2[q * 4 + 0], acc2[g]);
                acc2[g] = fmaf(w.y, xv2[q * 4 + 1], acc2[g]);
                acc2[g] = fmaf(w.z, xv2[q * 4 + 2], acc2[g]);
                acc2[g] = fmaf(w.w, xv2[q * 4 + 3], acc2[g]);
            }
        }
#pragma unroll
        for (int g = 0; g < GG; ++g) {
            psum1[(g * NWARP + ws) * BB + lane] = acc1[g];
            psum2[(g * NWARP + ws) * BB + lane] = acc2[g];
        }
        __syncthreads();

        if (tid < GG * BB) {
            // thread owns (b=lane, mloc=ws): reduce K-splits, run both GLIF calls
            float h1 = 0.f, h2 = 0.f;
#pragma unroll
            for (int s = 0; s < NWARP; ++s) {
                h1 += psum1[(ws * NWARP + s) * BB + lane];
                h2 += psum2[(ws * NWARP + s) * BB + lane];
            }
            // call A (feedforward input) -> sp_a  (output only)
            I1 = I1 * CID + CIA * h1;
            V1 = V1 * CVD + CVA * (I1 + A10 + A11);
            float spa = 20.0f / (1.0f + expf((TH - V1) * 0.1f));
            A10 = A10 * AD0 + AA0 * spa;
            A11 = A11 * AD1 + AA1 * spa;
            // call B (recurrent input) -> sp_b  (output + next-step recurrent src)
            I1 = I1 * CID + CIA * h2;
            V1 = V1 * CVD + CVA * (I1 + A10 + A11);
            float spb = 20.0f / (1.0f + expf((TH - V1) * 0.1f));
            A10 = A10 * AD0 + AA0 * spb;
            A11 = A11 * AD1 + AA1 * spb;

            const int m = mbase + ws;
            out[(2 * t)     * (BB * NN1) + lane * NN1 + m] = spa;
            out[(2 * t + 1) * (BB * NN1) + lane * NN1 + m] = spb;
            g_spbuf[t & 1][m * BB + lane] = spb;
        } else if (tid < GG * BB + 64) {
            // layer-0 GLIF on raw input: 64 (b, n0) elements per CTA
            I0 = I0 * CID + CIA * x0;
            V0 = V0 * CVD + CVA * (I0 + A00 + A01);
            float s = 20.0f / (1.0f + expf((TH - V0) * 0.1f));
            A00 = A00 * AD0 + AA0 * s;
            A01 = A01 * AD1 + AA1 * s;
            g_s0buf[t & 1][l0n * BB + l0b] = s;
        }

        if (t + 1 < TSTEPS) GRID_BARRIER(t + 1);
    }
#undef GRID_BARRIER
}

extern "C" void kernel_launch(void* const* d_in, const int* in_sizes, int n_in,
                              void* d_out, int out_size) {
    const float* inp = (const float*)d_in[0];
    const float* W1  = (const float*)d_in[1];
    const float* Wr  = (const float*)d_in[2];
    float* out       = (float*)d_out;
    rsnn_kernel<<<NCTA, NTHR>>>(inp, W1, Wr, out);
}

// round 3
// speedup vs baseline: 1.0114x; 1.0114x over previous
#include <cuda_runtime.h>
#include <math.h>

#define NCTA   128
#define NTHR   512
#define NWARP  16
#define TSTEPS 1000
#define BB     32
#define NN0    256
#define NN1    512
#define GG     4
#define NBARS  1000ULL
#define BARM   (NBARS * (unsigned long long)NCTA)

typedef unsigned long long u64;

// Cross-step exchange buffers (ping-pong), layout [neuron][batch] (128B rows),
// plus the monotonic grid-barrier counter.
__device__ float g_s0buf[2][NN0 * BB];
__device__ float g_spbuf[2][NN1 * BB];
__device__ unsigned long long g_arrive;

// ---- f32x2 helpers (packed dual fp32, fma pipe 2x) ----
__device__ __forceinline__ u64 pk2(float a, float b) {
    u64 r; asm("mov.b64 %0, {%1,%2};" : "=l"(r) : "f"(a), "f"(b)); return r;
}
__device__ __forceinline__ u64 ffma2(u64 a, u64 b, u64 c) {
    u64 d; asm("fma.rn.f32x2 %0, %1, %2, %3;" : "=l"(d) : "l"(a), "l"(b), "l"(c)); return d;
}
__device__ __forceinline__ u64 add2(u64 a, u64 b) {
    u64 d; asm("add.rn.f32x2 %0, %1, %2;" : "=l"(d) : "l"(a), "l"(b)); return d;
}
__device__ __forceinline__ void upk2(u64 v, float& a, float& b) {
    asm("mov.b64 {%0,%1}, %2;" : "=f"(a), "=f"(b) : "l"(v));
}
__device__ __forceinline__ u64 shfl_xor_u64(u64 v, int m) {
    unsigned lo = (unsigned)v, hi = (unsigned)(v >> 32);
    lo = __shfl_xor_sync(0xffffffffu, lo, m);
    hi = __shfl_xor_sync(0xffffffffu, hi, m);
    return ((u64)hi << 32) | lo;
}

__global__ void __launch_bounds__(NTHR, 1)
rsnn_kernel(const float* __restrict__ inp,
            const float* __restrict__ W1,
            const float* __restrict__ Wr,
            float* __restrict__ out)
{
    __shared__ float wp1[NN0 * GG];                 // 4 KB  prepacked [n][g]
    __shared__ float wpr[NN1 * GG];                 // 8 KB  prepacked [n][g]
    __shared__ float psum1[2 * NWARP * GG * BB];    // 16 KB (32 splits x 128)
    __shared__ float psum2[2 * NWARP * GG * BB];    // 16 KB
    __shared__ unsigned long long sh_base;

    const int tid   = threadIdx.x;
    const int cta   = blockIdx.x;
    const int ws    = tid >> 5;
    const int lane  = tid & 31;
    const int ng    = lane >> 3;      // 0..3 : n sub-slice within warp
    const int bg    = lane & 7;       // 0..7 : batch group (4 batches)
    const int mbase = cta * GG;

    // ---- one-time weight prepack: wp[n*4+g] = W[mbase+g][n] ----
    for (int i = tid; i < NN0 * GG; i += NTHR)
        wp1[i] = W1[(mbase + (i & 3)) * NN0 + (i >> 2)];
    for (int i = tid; i < NN1 * GG; i += NTHR)
        wpr[i] = Wr[(mbase + (i & 3)) * NN1 + (i >> 2)];

    // ---- launch-consistent barrier base ----
    if (tid == 0) {
        unsigned long long g = *(volatile unsigned long long*)&g_arrive;
        sh_base = (g / BARM) * BARM;
    }

    // ---- zero the parity-1 buffers (initial delayed state) ----
    {
        const int per   = (NN0 * BB + NN1 * BB) / NCTA;  // 192
        const int start = cta * per;
        for (int i = tid; i < per; i += NTHR) {
            int idx = start + i;
            if (idx < NN0 * BB) g_s0buf[1][idx] = 0.0f;
            else                g_spbuf[1][idx - NN0 * BB] = 0.0f;
        }
    }
    __syncthreads();
    const unsigned long long base = sh_base;

#define GRID_BARRIER(bid) do {                                                   \
        __syncthreads();                                                         \
        if (tid == 0) {                                                          \
            __threadfence();                                                     \
            atomicAdd(&g_arrive, 1ULL);                                          \
            unsigned long long tgt =                                             \
                base + (unsigned long long)((bid) + 1) * NCTA;                   \
            while (*(volatile unsigned long long*)&g_arrive < tgt) {             \
                __nanosleep(20);                                                 \
            }                                                                    \
            __threadfence();                                                     \
        }                                                                        \
        __syncthreads();                                                         \
    } while (0)

    // ---- GLIF constants ----
    const float CID = 0.95f;
    const float CIA = 0.05f;
    const float CVD = 0.99f;
    const float CVA = (float)(0.05 * (1.0 / 5.0) * (1.0 / 9.43));
    const float TH  = (float)(10.0 * 1.0986122886681098);
    const float AD0 = (float)(1.0 - 0.05 * 0.003);
    const float AD1 = (float)(1.0 - 0.05 * 0.1);
    const float AA0 = (float)(-9.18 * 0.05);
    const float AA1 = (float)(-198.94 * 0.05);

    // ---- recurrent state in registers ----
    float V1 = 0.f, I1 = 0.f, A10 = 0.f, A11 = 0.f;   // layer-1 (tid < 128)
    float V0 = 0.f, I0 = 0.f, A00 = 0.f, A01 = 0.f;   // layer-0 (tid 128..191)

    // reducer role mapping (tid < 128): g = tid>>5, b = tid&31
    const int rg = tid >> 5;
    const int rb = tid & 31;

    // layer-0 element (tid 128..191)
    const int l0id = cta * 64 + (tid - 128);
    const int l0b  = l0id >> 8;
    const int l0n  = l0id & 255;

    const int nb1 = ws * (NN0 / NWARP);   // 16-wide n slice (GEMM1)
    const int nb2 = ws * (NN1 / NWARP);   // 32-wide n slice (GEMM2)

    GRID_BARRIER(0);

    for (int t = 0; t < TSTEPS; ++t) {
        const float* __restrict__ s0r = g_s0buf[(t & 1) ^ 1];
        const float* __restrict__ spr = g_spbuf[(t & 1) ^ 1];

        // hoist layer-0 input load (DRAM latency overlaps GEMM)
        float x0 = 0.0f;
        if (tid >= 128 && tid < 192)
            x0 = __ldg(&inp[t * (BB * NN0) + l0b * NN0 + l0n]);

        // ---- GEMM: each thread computes a 4g x 4b tile, split over n ----
        // acc[g*2+p] = f32x2 over batch pair p of (4bg+2p, 4bg+2p+1)
        u64 acc1[8], acc2[8];
#pragma unroll
        for (int i = 0; i < 8; ++i) { acc1[i] = 0ULL; acc2[i] = 0ULL; }

#pragma unroll
        for (int k = 0; k < 4; ++k) {          // GEMM1: n = nb1 + k*4 + ng
            const int n = nb1 + k * 4 + ng;
            float4 x4 = __ldcg((const float4*)(s0r + n * BB + bg * 4));
            float4 w4 = *(const float4*)(wp1 + n * 4);
            u64 x01 = pk2(x4.x, x4.y), x23 = pk2(x4.z, x4.w);
            u64 w0 = pk2(w4.x, w4.x), w1 = pk2(w4.y, w4.y);
            u64 w2 = pk2(w4.z, w4.z), w3 = pk2(w4.w, w4.w);
            acc1[0] = ffma2(w0, x01, acc1[0]); acc1[1] = ffma2(w0, x23, acc1[1]);
            acc1[2] = ffma2(w1, x01, acc1[2]); acc1[3] = ffma2(w1, x23, acc1[3]);
            acc1[4] = ffma2(w2, x01, acc1[4]); acc1[5] = ffma2(w2, x23, acc1[5]);
            acc1[6] = ffma2(w3, x01, acc1[6]); acc1[7] = ffma2(w3, x23, acc1[7]);
        }
#pragma unroll
        for (int k = 0; k < 8; ++k) {          // GEMM2: n = nb2 + k*4 + ng
            const int n = nb2 + k * 4 + ng;
            float4 x4 = __ldcg((const float4*)(spr + n * BB + bg * 4));
            float4 w4 = *(const float4*)(wpr + n * 4);
            u64 x01 = pk2(x4.x, x4.y), x23 = pk2(x4.z, x4.w);
            u64 w0 = pk2(w4.x, w4.x), w1 = pk2(w4.y, w4.y);
            u64 w2 = pk2(w4.z, w4.z), w3 = pk2(w4.w, w4.w);
            acc2[0] = ffma2(w0, x01, acc2[0]); acc2[1] = ffma2(w0, x23, acc2[1]);
            acc2[2] = ffma2(w1, x01, acc2[2]); acc2[3] = ffma2(w1, x23, acc2[3]);
            acc2[4] = ffma2(w2, x01, acc2[4]); acc2[5] = ffma2(w2, x23, acc2[5]);
            acc2[6] = ffma2(w3, x01, acc2[6]); acc2[7] = ffma2(w3, x23, acc2[7]);
        }

        // ---- one butterfly step over ng pairs (lanes xor 8) ----
#pragma unroll
        for (int i = 0; i < 8; ++i) {
            acc1[i] = add2(acc1[i], shfl_xor_u64(acc1[i], 8));
            acc2[i] = add2(acc2[i], shfl_xor_u64(acc2[i], 8));
        }

        // ---- psum stores: 32 splits (16 warps x 2 ng-halves) ----
        if ((ng & 1) == 0) {
            const int sbase = (ws * 2 + (ng >> 1)) * (GG * BB) + bg * 4;
#pragma unroll
            for (int g = 0; g < GG; ++g) {
                float4 v1, v2;
                upk2(acc1[g * 2],     v1.x, v1.y); upk2(acc1[g * 2 + 1], v1.z, v1.w);
                upk2(acc2[g * 2],     v2.x, v2.y); upk2(acc2[g * 2 + 1], v2.z, v2.w);
                *(float4*)&psum1[sbase + g * BB] = v1;
                *(float4*)&psum2[sbase + g * BB] = v2;
            }
        }
        __syncthreads();

        if (tid < 128) {
            // reduce 32 splits for (g=rg, b=rb), then both GLIF calls
            float h1a = 0.f, h1b = 0.f, h2a = 0.f, h2b = 0.f;
#pragma unroll
            for (int s = 0; s < 32; s += 2) {
                h1a += psum1[s * (GG * BB) + rg * BB + rb];
                h1b += psum1[(s + 1) * (GG * BB) + rg * BB + rb];
                h2a += psum2[s * (GG * BB) + rg * BB + rb];
                h2b += psum2[(s + 1) * (GG * BB) + rg * BB + rb];
            }
            const float h1 = h1a + h1b, h2 = h2a + h2b;

            // call A (feedforward) -> sp_a
            I1 = I1 * CID + CIA * h1;
            V1 = V1 * CVD + CVA * (I1 + A10 + A11);
            float spa = 20.0f / (1.0f + __expf((TH - V1) * 0.1f));
            A10 = A10 * AD0 + AA0 * spa;
            A11 = A11 * AD1 + AA1 * spa;
            // call B (recurrent) -> sp_b
            I1 = I1 * CID + CIA * h2;
            V1 = V1 * CVD + CVA * (I1 + A10 + A11);
            float spb = 20.0f / (1.0f + __expf((TH - V1) * 0.1f));
            A10 = A10 * AD0 + AA0 * spb;
            A11 = A11 * AD1 + AA1 * spb;

            const int m = mbase + rg;
            out[(2 * t)     * (BB * NN1) + rb * NN1 + m] = spa;
            out[(2 * t + 1) * (BB * NN1) + rb * NN1 + m] = spb;
            g_spbuf[t & 1][m * BB + rb] = spb;
        } else if (tid < 192) {
            // layer-0 GLIF on raw input
            I0 = I0 * CID + CIA * x0;
            V0 = V0 * CVD + CVA * (I0 + A00 + A01);
            float s = 20.0f / (1.0f + __expf((TH - V0) * 0.1f));
            A00 = A00 * AD0 + AA0 * s;
            A01 = A01 * AD1 + AA1 * s;
            g_s0buf[t & 1][l0n * BB + l0b] = s;
        }

        if (t + 1 < TSTEPS) GRID_BARRIER(t + 1);
    }
#undef GRID_BARRIER
}

extern "C" void kernel_launch(void* const* d_in, const int* in_sizes, int n_in,
                              void* d_out, int out_size) {
    const float* inp = (const float*)d_in[0];
    const float* W1  = (const float*)d_in[1];
    const float* Wr  = (const float*)d_in[2];
    float* out       = (float*)d_out;
    rsnn_kernel<<<NCTA, NTHR>>>(inp, W1, Wr, out);
}

// round 4
// speedup vs baseline: 1.0590x; 1.0470x over previous
#include <cuda_runtime.h>
#include <math.h>

#define NCTA   128
#define NTHR   512
#define NWARP  16
#define TSTEPS 1000
#define BB     32
#define NN0    256
#define NN1    512
#define GG     4
#define NSPLIT 16
#define NBARS  1000ULL
#define BARM   (NBARS * (unsigned long long)NCTA)

typedef unsigned long long u64;

// Cross-step exchange buffers (ping-pong), layout [neuron][batch] (128B rows),
// plus the monotonic grid-barrier counter.
__device__ float g_s0buf[2][NN0 * BB];
__device__ float g_spbuf[2][NN1 * BB];
__device__ unsigned long long g_arrive;

// ---- f32x2 helpers (packed dual fp32, fma pipe 2x) ----
__device__ __forceinline__ u64 pk2(float a, float b) {
    u64 r; asm("mov.b64 %0, {%1,%2};" : "=l"(r) : "f"(a), "f"(b)); return r;
}
__device__ __forceinline__ u64 ffma2(u64 a, u64 b, u64 c) {
    u64 d; asm("fma.rn.f32x2 %0, %1, %2, %3;" : "=l"(d) : "l"(a), "l"(b), "l"(c)); return d;
}
__device__ __forceinline__ u64 add2(u64 a, u64 b) {
    u64 d; asm("add.rn.f32x2 %0, %1, %2;" : "=l"(d) : "l"(a), "l"(b)); return d;
}
__device__ __forceinline__ void upk2(u64 v, float& a, float& b) {
    asm("mov.b64 {%0,%1}, %2;" : "=f"(a), "=f"(b) : "l"(v));
}
__device__ __forceinline__ u64 shfl_xor_u64(u64 v, int m) {
    unsigned lo = (unsigned)v, hi = (unsigned)(v >> 32);
    lo = __shfl_xor_sync(0xffffffffu, lo, m);
    hi = __shfl_xor_sync(0xffffffffu, hi, m);
    return ((u64)hi << 32) | lo;
}

__global__ void __launch_bounds__(NTHR, 1)
rsnn_kernel(const float* __restrict__ inp,
            const float* __restrict__ W1,
            const float* __restrict__ Wr,
            float* __restrict__ out)
{
    __shared__ float wp1[NN0 * GG];               // 4 KB  prepacked [n][g]
    __shared__ float wpr[NN1 * GG];               // 8 KB  prepacked [n][g]
    __shared__ float psum1[NSPLIT * GG * BB];     // 8 KB  (16 splits x 128)
    __shared__ float psum2[NSPLIT * GG * BB];     // 8 KB
    __shared__ float sta[BB * GG];                // 512 B staged spa [b][g]
    __shared__ float stb[BB * GG];                // 512 B staged spb [b][g]
    __shared__ unsigned long long sh_base;

    const int tid   = threadIdx.x;
    const int cta   = blockIdx.x;
    const int ws    = tid >> 5;
    const int lane  = tid & 31;
    const int ng    = lane >> 3;      // 0..3 : n sub-slice within warp
    const int bg    = lane & 7;       // 0..7 : batch group (4 batches)
    const int mbase = cta * GG;

    // ---- one-time weight prepack: wp[n*4+g] = W[mbase+g][n] ----
    for (int i = tid; i < NN0 * GG; i += NTHR)
        wp1[i] = W1[(mbase + (i & 3)) * NN0 + (i >> 2)];
    for (int i = tid; i < NN1 * GG; i += NTHR)
        wpr[i] = Wr[(mbase + (i & 3)) * NN1 + (i >> 2)];

    // ---- launch-consistent barrier base ----
    if (tid == 0) {
        unsigned long long g = *(volatile unsigned long long*)&g_arrive;
        sh_base = (g / BARM) * BARM;
    }

    // ---- zero the parity-1 buffers (initial delayed state) ----
    {
        const int per   = (NN0 * BB + NN1 * BB) / NCTA;  // 192
        const int start = cta * per;
        for (int i = tid; i < per; i += NTHR) {
            int idx = start + i;
            if (idx < NN0 * BB) g_s0buf[1][idx] = 0.0f;
            else                g_spbuf[1][idx - NN0 * BB] = 0.0f;
        }
    }
    __syncthreads();
    const unsigned long long base = sh_base;

    // ---- GLIF constants ----
    const float CID = 0.95f;
    const float CIA = 0.05f;
    const float CVD = 0.99f;
    const float CVA = (float)(0.05 * (1.0 / 5.0) * (1.0 / 9.43));
    const float TH  = (float)(10.0 * 1.0986122886681098);
    const float AD0 = (float)(1.0 - 0.05 * 0.003);
    const float AD1 = (float)(1.0 - 0.05 * 0.1);
    const float AA0 = (float)(-9.18 * 0.05);
    const float AA1 = (float)(-198.94 * 0.05);

    // ---- recurrent state in registers ----
    float V1 = 0.f, I1 = 0.f, A10 = 0.f, A11 = 0.f;   // layer-1 (tid < 128)
    float V0 = 0.f, I0 = 0.f, A00 = 0.f, A01 = 0.f;   // layer-0 (tid 128..191)

    // reducer role mapping (tid < 128): g = tid>>5, b = tid&31
    const int rg = tid >> 5;
    const int rb = tid & 31;

    // layer-0 element (tid 128..191)
    const bool isl0 = (tid >= 128 && tid < 192);
    const int l0id = cta * 64 + (tid - 128);
    const int l0b  = l0id >> 8;
    const int l0n  = l0id & 255;

    const int nb1 = ws * (NN0 / NWARP);   // 16-wide n slice (GEMM1)
    const int nb2 = ws * (NN1 / NWARP);   // 32-wide n slice (GEMM2)

    // initial barrier (id 0)
    __syncthreads();
    if (tid == 0) {
        __threadfence();
        atomicAdd(&g_arrive, 1ULL);
        while (*(volatile unsigned long long*)&g_arrive < base + NCTA) { }
        __threadfence();
    }
    // prefetch layer-0 input for t = 0 while barrier settles
    float x0 = 0.0f;
    if (isl0) x0 = __ldg(&inp[l0b * NN0 + l0n]);
    __syncthreads();

    for (int t = 0; t < TSTEPS; ++t) {
        const float* __restrict__ s0r = g_s0buf[(t & 1) ^ 1];
        const float* __restrict__ spr = g_spbuf[(t & 1) ^ 1];

        // ---- GEMM: each thread computes a 4g x 4b tile, split over n ----
        u64 acc1[8], acc2[8];
#pragma unroll
        for (int i = 0; i < 8; ++i) { acc1[i] = 0ULL; acc2[i] = 0ULL; }

#pragma unroll
        for (int k = 0; k < 4; ++k) {          // GEMM1: n = nb1 + k*4 + ng
            const int n = nb1 + k * 4 + ng;
            float4 x4 = __ldcg((const float4*)(s0r + n * BB + bg * 4));
            float4 w4 = *(const float4*)(wp1 + n * 4);
            u64 x01 = pk2(x4.x, x4.y), x23 = pk2(x4.z, x4.w);
            u64 w0 = pk2(w4.x, w4.x), w1 = pk2(w4.y, w4.y);
            u64 w2 = pk2(w4.z, w4.z), w3 = pk2(w4.w, w4.w);
            acc1[0] = ffma2(w0, x01, acc1[0]); acc1[1] = ffma2(w0, x23, acc1[1]);
            acc1[2] = ffma2(w1, x01, acc1[2]); acc1[3] = ffma2(w1, x23, acc1[3]);
            acc1[4] = ffma2(w2, x01, acc1[4]); acc1[5] = ffma2(w2, x23, acc1[5]);
            acc1[6] = ffma2(w3, x01, acc1[6]); acc1[7] = ffma2(w3, x23, acc1[7]);
        }
#pragma unroll
        for (int k = 0; k < 8; ++k) {          // GEMM2: n = nb2 + k*4 + ng
            const int n = nb2 + k * 4 + ng;
            float4 x4 = __ldcg((const float4*)(spr + n * BB + bg * 4));
            float4 w4 = *(const float4*)(wpr + n * 4);
            u64 x01 = pk2(x4.x, x4.y), x23 = pk2(x4.z, x4.w);
            u64 w0 = pk2(w4.x, w4.x), w1 = pk2(w4.y, w4.y);
            u64 w2 = pk2(w4.z, w4.z), w3 = pk2(w4.w, w4.w);
            acc2[0] = ffma2(w0, x01, acc2[0]); acc2[1] = ffma2(w0, x23, acc2[1]);
            acc2[2] = ffma2(w1, x01, acc2[2]); acc2[3] = ffma2(w1, x23, acc2[3]);
            acc2[4] = ffma2(w2, x01, acc2[4]); acc2[5] = ffma2(w2, x23, acc2[5]);
            acc2[6] = ffma2(w3, x01, acc2[6]); acc2[7] = ffma2(w3, x23, acc2[7]);
        }

        // ---- two butterfly levels over ng (xor 8, xor 16): full n-sum per warp ----
#pragma unroll
        for (int i = 0; i < 8; ++i) {
            acc1[i] = add2(acc1[i], shfl_xor_u64(acc1[i], 8));
            acc2[i] = add2(acc2[i], shfl_xor_u64(acc2[i], 8));
            acc1[i] = add2(acc1[i], shfl_xor_u64(acc1[i], 16));
            acc2[i] = add2(acc2[i], shfl_xor_u64(acc2[i], 16));
        }

        // ---- psum stores: 16 splits (one per warp), lanes ng==0 store ----
        if (ng == 0) {
            const int sbase = ws * (GG * BB) + bg * 4;
#pragma unroll
            for (int g = 0; g < GG; ++g) {
                float4 v1, v2;
                upk2(acc1[g * 2],     v1.x, v1.y); upk2(acc1[g * 2 + 1], v1.z, v1.w);
                upk2(acc2[g * 2],     v2.x, v2.y); upk2(acc2[g * 2 + 1], v2.z, v2.w);
                *(float4*)&psum1[sbase + g * BB] = v1;
                *(float4*)&psum2[sbase + g * BB] = v2;
            }
        }
        __syncthreads();

        if (tid < 128) {
            // reduce 16 splits for (g=rg, b=rb), then both GLIF calls
            float h1a = 0.f, h1b = 0.f, h2a = 0.f, h2b = 0.f;
#pragma unroll
            for (int s = 0; s < NSPLIT; s += 2) {
                h1a += psum1[s * (GG * BB) + rg * BB + rb];
                h1b += psum1[(s + 1) * (GG * BB) + rg * BB + rb];
                h2a += psum2[s * (GG * BB) + rg * BB + rb];
                h2b += psum2[(s + 1) * (GG * BB) + rg * BB + rb];
            }
            const float h1 = h1a + h1b, h2 = h2a + h2b;

            // call A (feedforward) -> sp_a
            I1 = I1 * CID + CIA * h1;
            V1 = V1 * CVD + CVA * (I1 + A10 + A11);
            float spa = 20.0f / (1.0f + __expf((TH - V1) * 0.1f));
            A10 = A10 * AD0 + AA0 * spa;
            A11 = A11 * AD1 + AA1 * spa;
            // call B (recurrent) -> sp_b
            I1 = I1 * CID + CIA * h2;
            V1 = V1 * CVD + CVA * (I1 + A10 + A11);
            float spb = 20.0f / (1.0f + __expf((TH - V1) * 0.1f));
            A10 = A10 * AD0 + AA0 * spb;
            A11 = A11 * AD1 + AA1 * spb;

            // exchange store (critical) + staging for coalesced out stores
            g_spbuf[t & 1][(mbase + rg) * BB + rb] = spb;
            sta[rb * GG + rg] = spa;
            stb[rb * GG + rg] = spb;
        } else if (isl0) {
            // layer-0 GLIF on (prefetched) raw input
            I0 = I0 * CID + CIA * x0;
            V0 = V0 * CVD + CVA * (I0 + A00 + A01);
            float s = 20.0f / (1.0f + __expf((TH - V0) * 0.1f));
            A00 = A00 * AD0 + AA0 * s;
            A01 = A01 * AD1 + AA1 * s;
            g_s0buf[t & 1][l0n * BB + l0b] = s;
        }

        // ================= split-phase grid barrier =================
        __syncthreads();                      // exchange + staging complete
        if (tid == 0) {                       // ARRIVE early
            __threadfence();
            atomicAdd(&g_arrive, 1ULL);
        }
        // work that nothing downstream (cross-CTA) depends on, done in the
        // wait window: coalesced out stores + next-step input prefetch
        if (ws == 0) {
            *(float4*)&out[(2 * t) * (BB * NN1) + lane * NN1 + mbase] =
                *(const float4*)&sta[lane * GG];
        } else if (ws == 1) {
            *(float4*)&out[(2 * t + 1) * (BB * NN1) + lane * NN1 + mbase] =
                *(const float4*)&stb[lane * GG];
        }
        if (isl0 && t + 1 < TSTEPS)
            x0 = __ldg(&inp[(t + 1) * (BB * NN0) + l0b * NN0 + l0n]);
        if (t + 1 < TSTEPS) {
            if (tid == 0) {                   // WAIT (pure spin, no nanosleep)
                const unsigned long long tgt =
                    base + (unsigned long long)(t + 2) * NCTA;
                while (*(volatile unsigned long long*)&g_arrive < tgt) { }
                __threadfence();
            }
            __syncthreads();
        }
    }
}

extern "C" void kernel_launch(void* const* d_in, const int* in_sizes, int n_in,
                              void* d_out, int out_size) {
    const float* inp = (const float*)d_in[0];
    const float* W1  = (const float*)d_in[1];
    const float* Wr  = (const float*)d_in[2];
    float* out       = (float*)d_out;
    rsnn_kernel<<<NCTA, NTHR>>>(inp, W1, Wr, out);
}